// round 9
// baseline (speedup 1.0000x reference)
#include <cuda_runtime.h>
#include <math_constants.h>
#include <cstdint>

// Problem constants
#define SEQ   1024
#define BATCH 8
#define EMB   1024
#define NH    16
#define HD    64
#define MROWS (SEQ*BATCH)        // 8192
#define NHEADS_TOT (BATCH*NH)    // 128

// ---------------------------------------------------------------------------
// Scratch (device globals; allocation-free)
// ---------------------------------------------------------------------------
__device__ float g_Q[NHEADS_TOT * SEQ * HD];   // [n][s][d], pre-scaled by 1/8
__device__ float g_K[NHEADS_TOT * SEQ * HD];
__device__ float g_V[NHEADS_TOT * SEQ * HD];
__device__ float g_Xhi[MROWS * EMB];
__device__ float g_Xlo[MROWS * EMB];
__device__ float g_Wqhi[3 * EMB * EMB];
__device__ float g_Wqlo[3 * EMB * EMB];
__device__ float g_Wohi[EMB * EMB];
__device__ float g_Wolo[EMB * EMB];
__device__ float g_Chi[MROWS * EMB];           // ctx hi split, [s,b,e]
__device__ float g_Clo[MROWS * EMB];           // ctx lo split

// ---------------------------------------------------------------------------
// Helpers (sm_103 plain: mma.sync + cp.async only; NO tcgen05 anywhere)
// ---------------------------------------------------------------------------
__device__ __forceinline__ uint32_t smem_u32(const void* p) {
    uint32_t a;
    asm("{ .reg .u64 t; cvta.to.shared.u64 t, %1; cvt.u32.u64 %0, t; }"
        : "=r"(a) : "l"(p));
    return a;
}

__device__ __forceinline__ void cp16(uint32_t dst, const float* src) {
    asm volatile("cp.async.cg.shared.global [%0], [%1], 16;" :: "r"(dst), "l"(src));
}

__device__ __forceinline__ float tf32_rna(float x) {
    uint32_t u;
    asm("cvt.rna.tf32.f32 %0, %1;" : "=r"(u) : "f"(x));
    return __uint_as_float(u);
}

// D += A(16x8,row) * B(8x8,col) ; tf32 operands, f32 accum
__device__ __forceinline__ void mma8(float* c, const uint32_t* a, const uint32_t* b) {
    asm volatile(
        "mma.sync.aligned.m16n8k8.row.col.f32.tf32.tf32.f32 "
        "{%0,%1,%2,%3}, {%4,%5,%6,%7}, {%8,%9}, {%0,%1,%2,%3};"
        : "+f"(c[0]), "+f"(c[1]), "+f"(c[2]), "+f"(c[3])
        : "r"(a[0]), "r"(a[1]), "r"(a[2]), "r"(a[3]), "r"(b[0]), "r"(b[1]));
}

// ---------------------------------------------------------------------------
// Split kernel: x -> (hi = tf32(x), lo = tf32(x - hi))
// ---------------------------------------------------------------------------
__global__ __launch_bounds__(256) void split_kernel(
    const float4* __restrict__ src, float4* __restrict__ hi,
    float4* __restrict__ lo, int n4)
{
    int i = blockIdx.x * 256 + threadIdx.x;
    if (i >= n4) return;
    float4 x = src[i];
    float4 h, l;
    h.x = tf32_rna(x.x); l.x = tf32_rna(x.x - h.x);
    h.y = tf32_rna(x.y); l.y = tf32_rna(x.y - h.y);
    h.z = tf32_rna(x.z); l.z = tf32_rna(x.z - h.z);
    h.w = tf32_rna(x.w); l.w = tf32_rna(x.w - h.w);
    hi[i] = h; lo[i] = l;
}

// ---------------------------------------------------------------------------
// tf32x3 GEMM via mma.sync: C[M,N] = A[M,1024] @ B[N,1024]^T + bias[N]
// Block tile 128x128, BK=32, 2-stage cp.async pipeline, **512 threads**.
// 16 warps in 4(m)x4(n); warp tile 32x32 = 2x4 m16n8k8 tiles.
// 3 MMAs per tile per k8: Ahi*Bhi + Ahi*Blo + Alo*Bhi.
// ---------------------------------------------------------------------------
#define BKF   32
#define ASTR  36
#define T_OFF (128*ASTR)
#define STAGE_F (4*T_OFF)
#define G_SMEM (2*STAGE_F*4)      // 147456 bytes
#define NCHUNK (1024/BKF)

template<int MODE>
__global__ __launch_bounds__(512, 1)
void tc_gemm(const float* __restrict__ Ahi, const float* __restrict__ Alo,
             const float* __restrict__ Bhi, const float* __restrict__ Blo,
             const float* __restrict__ bias, float* __restrict__ Cout)
{
    extern __shared__ float sm[];
    const int tid  = threadIdx.x;
    const int wid  = tid >> 5;
    const int lane = tid & 31;
    const int m0 = blockIdx.y * 128;
    const int n0 = blockIdx.x * 128;
    const int warp_m = (wid & 3) * 32;
    const int warp_n = (wid >> 2) * 32;
    const int lr = lane >> 2;
    const int lc = lane & 3;

    float acc[2][4][4];
    #pragma unroll
    for (int mt = 0; mt < 2; mt++)
        #pragma unroll
        for (int nt = 0; nt < 4; nt++)
            #pragma unroll
            for (int r = 0; r < 4; r++) acc[mt][nt][r] = 0.0f;

    const uint32_t smb = smem_u32(sm);

    // chunk loader: 4 tensors x 128 rows x 8 quads; 2 cp16 per thread per tensor
    auto load_chunk = [&](int st, int k0) {
        const uint32_t sb = smb + (uint32_t)st * (STAGE_F * 4);
        #pragma unroll
        for (int i = 0; i < 2; i++) {
            const int idx = tid + i * 512;
            const int r = idx >> 3, q = idx & 7;
            const uint32_t o = (uint32_t)r * (ASTR * 4) + (uint32_t)q * 16;
            const size_t ga = (size_t)(m0 + r) * 1024 + k0 + q * 4;
            const size_t gb = (size_t)(n0 + r) * 1024 + k0 + q * 4;
            cp16(sb + 0 * (T_OFF * 4) + o, Ahi + ga);
            cp16(sb + 1 * (T_OFF * 4) + o, Alo + ga);
            cp16(sb + 2 * (T_OFF * 4) + o, Bhi + gb);
            cp16(sb + 3 * (T_OFF * 4) + o, Blo + gb);
        }
        asm volatile("cp.async.commit_group;" ::: "memory");
    };

    load_chunk(0, 0);
    load_chunk(1, BKF);

    for (int c = 0; c < NCHUNK; c++) {
        if (c < NCHUNK - 1) asm volatile("cp.async.wait_group 1;" ::: "memory");
        else                asm volatile("cp.async.wait_group 0;" ::: "memory");
        __syncthreads();

        const float* As_hi = sm + (c & 1) * STAGE_F;
        const float* As_lo = As_hi + T_OFF;
        const float* Bs_hi = As_hi + 2 * T_OFF;
        const float* Bs_lo = As_hi + 3 * T_OFF;

        #pragma unroll
        for (int kk = 0; kk < BKF; kk += 8) {
            uint32_t ah[2][4], al[2][4], bh[4][2], bl[4][2];
            #pragma unroll
            for (int mt = 0; mt < 2; mt++) {
                const int r = warp_m + mt * 16 + lr;
                const float* p  = As_hi + r * ASTR + kk + lc;
                const float* pl = As_lo + r * ASTR + kk + lc;
                ah[mt][0] = __float_as_uint(p[0]);
                ah[mt][1] = __float_as_uint(p[8 * ASTR]);
                ah[mt][2] = __float_as_uint(p[4]);
                ah[mt][3] = __float_as_uint(p[8 * ASTR + 4]);
                al[mt][0] = __float_as_uint(pl[0]);
                al[mt][1] = __float_as_uint(pl[8 * ASTR]);
                al[mt][2] = __float_as_uint(pl[4]);
                al[mt][3] = __float_as_uint(pl[8 * ASTR + 4]);
            }
            #pragma unroll
            for (int nt = 0; nt < 4; nt++) {
                const int r = warp_n + nt * 8 + lr;
                const float* p  = Bs_hi + r * ASTR + kk + lc;
                const float* pl = Bs_lo + r * ASTR + kk + lc;
                bh[nt][0] = __float_as_uint(p[0]);
                bh[nt][1] = __float_as_uint(p[4]);
                bl[nt][0] = __float_as_uint(pl[0]);
                bl[nt][1] = __float_as_uint(pl[4]);
            }
            #pragma unroll
            for (int mt = 0; mt < 2; mt++)
                #pragma unroll
                for (int nt = 0; nt < 4; nt++) {
                    mma8(acc[mt][nt], ah[mt], bh[nt]);
                    mma8(acc[mt][nt], ah[mt], bl[nt]);
                    mma8(acc[mt][nt], al[mt], bh[nt]);
                }
        }
        __syncthreads();
        if (c + 2 < NCHUNK) load_chunk(c & 1, (c + 2) * BKF);
    }

    // ---- Epilogue: direct global stores (pairs of consecutive n) ----
    #pragma unroll
    for (int mt = 0; mt < 2; mt++) {
        #pragma unroll
        for (int nt = 0; nt < 4; nt++) {
            const int gm = m0 + warp_m + mt * 16 + lr;
            const int gn = n0 + warp_n + nt * 8 + lc * 2;
            #pragma unroll
            for (int half = 0; half < 2; half++) {
                const int m = gm + half * 8;
                const float v0 = acc[mt][nt][half * 2 + 0] + __ldg(&bias[gn]);
                const float v1 = acc[mt][nt][half * 2 + 1] + __ldg(&bias[gn + 1]);
                if (MODE == 0) {
                    const int s = m >> 3;
                    const int b = m & 7;
                    const int h = gn / 192;
                    const int cc = gn - h * 192;
                    const int w = cc >> 6;           // 0=Q,1=K,2=V (pair never straddles)
                    const int d = cc & 63;
                    const size_t idx = ((size_t)(b * NH + h) * SEQ + s) * HD + d;
                    if (w == 0)      { g_Q[idx] = v0 * 0.125f; g_Q[idx + 1] = v1 * 0.125f; }
                    else if (w == 1) { g_K[idx] = v0;          g_K[idx + 1] = v1; }
                    else             { g_V[idx] = v0;          g_V[idx + 1] = v1; }
                } else {
                    Cout[(size_t)m * 1024 + gn]     = v0;
                    Cout[(size_t)m * 1024 + gn + 1] = v1;
                }
            }
        }
    }
}

// ---------------------------------------------------------------------------
// Tensor-core flash attention (unchanged from R8 passing version).
// ---------------------------------------------------------------------------
#define XSTR 136
#define VSTRK 136
#define ATTN2_SMEM (35584 * 4)

__global__ __launch_bounds__(256, 1) void attn_tc_kernel()
{
    extern __shared__ float sh[];
    float* Qd   = sh;                    // [64][136]  q-major, 2d+{hi,lo}
    float* Kd   = Qd + 64 * XSTR;        // [64][136]  k-major, 2d+{hi,lo}
    float* Vd   = Kd + 64 * XSTR;        // [64][136]  k-major, 2d+{hi,lo}
    float* Pd   = Vd + 64 * VSTRK;       // [64][136]  q-major, 2k+{hi,lo}
    float* wmax = Pd + 64 * XSTR;        // [4][64]
    float* wsum = wmax + 256;            // [4][64]
    float* mrun = wsum + 256;            // [64]
    float* lrun = mrun + 64;             // [64]
    float* ssc  = lrun + 64;             // [64]
    float* mnew = ssc + 64;              // [64]

    const int tid  = threadIdx.x;
    const int wid  = tid >> 5;
    const int lane = tid & 31;
    const int lr = lane >> 2;
    const int lc = lane & 3;
    const int n  = blockIdx.y;           // head (b*16+h)
    const int qt = blockIdx.x;
    const int warp_m = (wid & 1) * 32;
    const int warp_n = (wid >> 1) * 16;
    const int wcol   = wid >> 1;

    const float* Qg = g_Q + ((size_t)n * SEQ + qt * 64) * HD;
    const float* Kg = g_K + (size_t)n * SEQ * HD;
    const float* Vg = g_V + (size_t)n * SEQ * HD;

    // Stage Q (split, interleaved)
    for (int i = tid; i < 64 * 16; i += 256) {
        const int r = i >> 4, c4 = (i & 15) << 2;
        float4 v = *(const float4*)(Qg + r * HD + c4);
        float hx = tf32_rna(v.x), hy = tf32_rna(v.y);
        float hz = tf32_rna(v.z), hw = tf32_rna(v.w);
        float* q = &Qd[r * XSTR + c4 * 2];
        *(float4*)(q)     = make_float4(hx, tf32_rna(v.x - hx), hy, tf32_rna(v.y - hy));
        *(float4*)(q + 4) = make_float4(hz, tf32_rna(v.z - hz), hw, tf32_rna(v.w - hw));
    }
    if (tid < 64) { mrun[tid] = -CUDART_INF_F; lrun[tid] = 0.f; }
    __syncthreads();

    // Hoist Q fragments to registers (tile-invariant): qh/ql [mt][ks][4]
    uint32_t qh[2][8][4], ql[2][8][4];
    #pragma unroll
    for (int mt = 0; mt < 2; mt++) {
        const float* base = &Qd[(warp_m + mt * 16) * XSTR];
        #pragma unroll
        for (int ks = 0; ks < 8; ks++) {
            const int k2 = 2 * (ks * 8 + lc);
            uint2 f0 = *(const uint2*)&base[lr * XSTR + k2];
            uint2 f1 = *(const uint2*)&base[(lr + 8) * XSTR + k2];
            uint2 f2 = *(const uint2*)&base[lr * XSTR + k2 + 8];
            uint2 f3 = *(const uint2*)&base[(lr + 8) * XSTR + k2 + 8];
            qh[mt][ks][0] = f0.x; ql[mt][ks][0] = f0.y;
            qh[mt][ks][1] = f1.x; ql[mt][ks][1] = f1.y;
            qh[mt][ks][2] = f2.x; ql[mt][ks][2] = f2.y;
            qh[mt][ks][3] = f3.x; ql[mt][ks][3] = f3.y;
        }
    }

    float o[2][2][4];
    #pragma unroll
    for (int mt = 0; mt < 2; mt++)
        #pragma unroll
        for (int nt = 0; nt < 2; nt++)
            #pragma unroll
            for (int r = 0; r < 4; r++) o[mt][nt][r] = 0.f;

    for (int kt = 0; kt < 16; kt++) {
        __syncthreads();   // prev-iter readers of Kd/Vd/Pd done
        // Stage K,V (split, interleaved)
        for (int i = tid; i < 64 * 16; i += 256) {
            const int r = i >> 4, c4 = (i & 15) << 2;
            const size_t go = (size_t)(kt * 64 + r) * HD + c4;
            float4 kv = *(const float4*)(Kg + go);
            float4 vv = *(const float4*)(Vg + go);
            float hx, hy, hz, hw;
            hx = tf32_rna(kv.x); hy = tf32_rna(kv.y);
            hz = tf32_rna(kv.z); hw = tf32_rna(kv.w);
            float* kd = &Kd[r * XSTR + c4 * 2];
            *(float4*)(kd)     = make_float4(hx, tf32_rna(kv.x - hx), hy, tf32_rna(kv.y - hy));
            *(float4*)(kd + 4) = make_float4(hz, tf32_rna(kv.z - hz), hw, tf32_rna(kv.w - hw));
            hx = tf32_rna(vv.x); hy = tf32_rna(vv.y);
            hz = tf32_rna(vv.z); hw = tf32_rna(vv.w);
            float* vd = &Vd[r * VSTRK + c4 * 2];
            *(float4*)(vd)     = make_float4(hx, tf32_rna(vv.x - hx), hy, tf32_rna(vv.y - hy));
            *(float4*)(vd + 4) = make_float4(hz, tf32_rna(vv.z - hz), hw, tf32_rna(vv.w - hw));
        }
        __syncthreads();

        // ---- S = Q @ K^T (tf32x3) ----
        float s[2][2][4];
        #pragma unroll
        for (int mt = 0; mt < 2; mt++)
            #pragma unroll
            for (int nt = 0; nt < 2; nt++)
                #pragma unroll
                for (int r = 0; r < 4; r++) s[mt][nt][r] = 0.f;

        #pragma unroll
        for (int ks = 0; ks < 8; ks++) {
            uint32_t bh[2][2], bl[2][2];
            #pragma unroll
            for (int nt = 0; nt < 2; nt++) {
                const float* kb = &Kd[(warp_n + nt * 8 + lr) * XSTR + 2 * (ks * 8 + lc)];
                uint2 f0 = *(const uint2*)kb;
                uint2 f1 = *(const uint2*)(kb + 8);
                bh[nt][0] = f0.x; bl[nt][0] = f0.y;
                bh[nt][1] = f1.x; bl[nt][1] = f1.y;
            }
            #pragma unroll
            for (int mt = 0; mt < 2; mt++)
                #pragma unroll
                for (int nt = 0; nt < 2; nt++) {
                    mma8(s[mt][nt], qh[mt][ks], bh[nt]);
                    mma8(s[mt][nt], qh[mt][ks], bl[nt]);
                    mma8(s[mt][nt], ql[mt][ks], bh[nt]);
                }
        }

        // ---- row max partials ----
        #pragma unroll
        for (int mt = 0; mt < 2; mt++) {
            float m0 = fmaxf(fmaxf(s[mt][0][0], s[mt][0][1]), fmaxf(s[mt][1][0], s[mt][1][1]));
            float m1 = fmaxf(fmaxf(s[mt][0][2], s[mt][0][3]), fmaxf(s[mt][1][2], s[mt][1][3]));
            m0 = fmaxf(m0, __shfl_xor_sync(0xffffffffu, m0, 1));
            m0 = fmaxf(m0, __shfl_xor_sync(0xffffffffu, m0, 2));
            m1 = fmaxf(m1, __shfl_xor_sync(0xffffffffu, m1, 1));
            m1 = fmaxf(m1, __shfl_xor_sync(0xffffffffu, m1, 2));
            if (lc == 0) {
                wmax[wcol * 64 + warp_m + mt * 16 + lr]     = m0;
                wmax[wcol * 64 + warp_m + mt * 16 + lr + 8] = m1;
            }
        }
        __syncthreads();
        if (tid < 64) {
            const float mo = mrun[tid];
            float mn = fmaxf(fmaxf(wmax[tid], wmax[64 + tid]),
                             fmaxf(wmax[128 + tid], wmax[192 + tid]));
            mn = fmaxf(mn, mo);
            mnew[tid] = mn;
            ssc[tid]  = __expf(mo - mn);
            mrun[tid] = mn;
        }
        __syncthreads();

        // ---- P = exp(S - mnew), sums, store hi/lo, rescale O ----
        #pragma unroll
        for (int mt = 0; mt < 2; mt++) {
            const int r0 = warp_m + mt * 16 + lr;
            const float mn0 = mnew[r0], mn1 = mnew[r0 + 8];
            float ps0 = 0.f, ps1 = 0.f;
            #pragma unroll
            for (int nt = 0; nt < 2; nt++) {
                const float p0 = __expf(s[mt][nt][0] - mn0);
                const float p1 = __expf(s[mt][nt][1] - mn0);
                const float p2 = __expf(s[mt][nt][2] - mn1);
                const float p3 = __expf(s[mt][nt][3] - mn1);
                ps0 += p0 + p1; ps1 += p2 + p3;
                const float h0 = tf32_rna(p0), h1 = tf32_rna(p1);
                const float h2 = tf32_rna(p2), h3 = tf32_rna(p3);
                const int cbase = 2 * (warp_n + nt * 8 + 2 * lc);
                *(float4*)&Pd[r0 * XSTR + cbase] =
                    make_float4(h0, tf32_rna(p0 - h0), h1, tf32_rna(p1 - h1));
                *(float4*)&Pd[(r0 + 8) * XSTR + cbase] =
                    make_float4(h2, tf32_rna(p2 - h2), h3, tf32_rna(p3 - h3));
            }
            ps0 += __shfl_xor_sync(0xffffffffu, ps0, 1);
            ps0 += __shfl_xor_sync(0xffffffffu, ps0, 2);
            ps1 += __shfl_xor_sync(0xffffffffu, ps1, 1);
            ps1 += __shfl_xor_sync(0xffffffffu, ps1, 2);
            if (lc == 0) {
                wsum[wcol * 64 + r0]     = ps0;
                wsum[wcol * 64 + r0 + 8] = ps1;
            }
            const float sc0 = ssc[r0], sc1 = ssc[r0 + 8];
            #pragma unroll
            for (int nt = 0; nt < 2; nt++) {
                o[mt][nt][0] *= sc0; o[mt][nt][1] *= sc0;
                o[mt][nt][2] *= sc1; o[mt][nt][3] *= sc1;
            }
        }
        __syncthreads();
        if (tid < 64)
            lrun[tid] = lrun[tid] * ssc[tid]
                      + (wsum[tid] + wsum[64 + tid] + wsum[128 + tid] + wsum[192 + tid]);

        // ---- O += P @ V (P exact hi/lo, V hi/lo, 3 terms) ----
        #pragma unroll
        for (int ks = 0; ks < 8; ks++) {
            uint32_t vh[2][2], vl[2][2];
            #pragma unroll
            for (int nt = 0; nt < 2; nt++) {
                const float* vb = &Vd[(ks * 8 + lc) * VSTRK + 2 * (warp_n + nt * 8 + lr)];
                uint2 f0 = *(const uint2*)vb;
                uint2 f1 = *(const uint2*)(vb + 4 * VSTRK);
                vh[nt][0] = f0.x; vl[nt][0] = f0.y;
                vh[nt][1] = f1.x; vl[nt][1] = f1.y;
            }
            #pragma unroll
            for (int mt = 0; mt < 2; mt++) {
                const float* pb = &Pd[(warp_m + mt * 16) * XSTR];
                const int k2 = 2 * (ks * 8 + lc);
                uint2 f0 = *(const uint2*)&pb[lr * XSTR + k2];
                uint2 f1 = *(const uint2*)&pb[(lr + 8) * XSTR + k2];
                uint2 f2 = *(const uint2*)&pb[lr * XSTR + k2 + 8];
                uint2 f3 = *(const uint2*)&pb[(lr + 8) * XSTR + k2 + 8];
                uint32_t ph[4] = {f0.x, f1.x, f2.x, f3.x};
                uint32_t pl[4] = {f0.y, f1.y, f2.y, f3.y};
                #pragma unroll
                for (int nt = 0; nt < 2; nt++) {
                    mma8(o[mt][nt], ph, vh[nt]);
                    mma8(o[mt][nt], ph, vl[nt]);
                    mma8(o[mt][nt], pl, vh[nt]);
                }
            }
        }
    }

    __syncthreads();
    // Normalize and store ctx hi/lo splits to [s,b,e]
    const int b = n >> 4;
    const int h = n & 15;
    #pragma unroll
    for (int mt = 0; mt < 2; mt++) {
        const int r0 = warp_m + mt * 16 + lr;
        const float li0 = 1.0f / lrun[r0];
        const float li1 = 1.0f / lrun[r0 + 8];
        #pragma unroll
        for (int nt = 0; nt < 2; nt++) {
            const int d = warp_n + nt * 8 + 2 * lc;
            #pragma unroll
            for (int half = 0; half < 2; half++) {
                const int row = r0 + half * 8;
                const float li = half ? li1 : li0;
                const float v0 = o[mt][nt][half * 2 + 0] * li;
                const float v1 = o[mt][nt][half * 2 + 1] * li;
                const size_t addr = ((size_t)(qt * 64 + row) * BATCH + b) * EMB + h * HD + d;
                const float h0 = tf32_rna(v0), h1 = tf32_rna(v1);
                *(float2*)&g_Chi[addr] = make_float2(h0, h1);
                *(float2*)&g_Clo[addr] = make_float2(tf32_rna(v0 - h0), tf32_rna(v1 - h1));
            }
        }
    }
}

// ---------------------------------------------------------------------------
extern "C" void kernel_launch(void* const* d_in, const int* in_sizes, int n_in,
                              void* d_out, int out_size)
{
    const float* X  = (const float*)d_in[0];  // query [S,B,E]
    const float* Wq = (const float*)d_in[3];  // in_proj_w [3E,E]
    const float* bq = (const float*)d_in[4];  // in_proj_b [3E]
    const float* Wo = (const float*)d_in[5];  // out_proj_w [E,E]
    const float* bo = (const float*)d_in[6];  // out_proj_b [E]
    float* out = (float*)d_out;

    cudaFuncSetAttribute(attn_tc_kernel,
                         cudaFuncAttributeMaxDynamicSharedMemorySize, ATTN2_SMEM);
    cudaFuncSetAttribute(tc_gemm<0>,
                         cudaFuncAttributeMaxDynamicSharedMemorySize, G_SMEM);
    cudaFuncSetAttribute(tc_gemm<1>,
                         cudaFuncAttributeMaxDynamicSharedMemorySize, G_SMEM);

    float *xhi, *xlo, *wqhi, *wqlo, *wohi, *wolo, *chi, *clo;
    cudaGetSymbolAddress((void**)&xhi,  g_Xhi);
    cudaGetSymbolAddress((void**)&xlo,  g_Xlo);
    cudaGetSymbolAddress((void**)&wqhi, g_Wqhi);
    cudaGetSymbolAddress((void**)&wqlo, g_Wqlo);
    cudaGetSymbolAddress((void**)&wohi, g_Wohi);
    cudaGetSymbolAddress((void**)&wolo, g_Wolo);
    cudaGetSymbolAddress((void**)&chi,  g_Chi);
    cudaGetSymbolAddress((void**)&clo,  g_Clo);

    // 0) tf32 hi/lo splits of inputs and weights
    split_kernel<<<(MROWS*EMB/4 + 255)/256, 256>>>((const float4*)X, (float4*)xhi, (float4*)xlo, MROWS*EMB/4);
    split_kernel<<<(3*EMB*EMB/4 + 255)/256, 256>>>((const float4*)Wq, (float4*)wqhi, (float4*)wqlo, 3*EMB*EMB/4);
    split_kernel<<<(EMB*EMB/4 + 255)/256, 256>>>((const float4*)Wo, (float4*)wohi, (float4*)wolo, EMB*EMB/4);

    // 1) QKV projection (mma.sync tf32x3, 512 threads) + scatter
    tc_gemm<0><<<dim3(3072/128, MROWS/128), 512, G_SMEM>>>(xhi, xlo, wqhi, wqlo, bq, nullptr);

    // 2) Tensor-core flash attention — writes ctx hi/lo splits
    attn_tc_kernel<<<dim3(SEQ/64, NHEADS_TOT), 256, ATTN2_SMEM>>>();

    // 3) Output projection (mma.sync tf32x3, 512 threads)
    tc_gemm<1><<<dim3(1024/128, MROWS/128), 512, G_SMEM>>>(chi, clo, wohi, wolo, bo, out);
}

// round 10
// speedup vs baseline: 1.2889x; 1.2889x over previous
#include <cuda_runtime.h>
#include <cuda_bf16.h>
#include <math_constants.h>
#include <cstdint>

// Problem constants
#define SEQ   1024
#define BATCH 8
#define EMB   1024
#define NH    16
#define HD    64
#define MROWS (SEQ*BATCH)        // 8192
#define NHEADS_TOT (BATCH*NH)    // 128

// ---------------------------------------------------------------------------
// Scratch (device globals; allocation-free)
// ---------------------------------------------------------------------------
__device__ float g_Q[NHEADS_TOT * SEQ * HD];   // [n][s][d], pre-scaled by 1/8
__device__ float g_K[NHEADS_TOT * SEQ * HD];
__device__ float g_V[NHEADS_TOT * SEQ * HD];
__device__ __nv_bfloat16 g_Xh[MROWS * EMB];
__device__ __nv_bfloat16 g_Xm[MROWS * EMB];
__device__ __nv_bfloat16 g_Wqh[3 * EMB * EMB];
__device__ __nv_bfloat16 g_Wqm[3 * EMB * EMB];
__device__ __nv_bfloat16 g_Woh[EMB * EMB];
__device__ __nv_bfloat16 g_Wom[EMB * EMB];
__device__ __nv_bfloat16 g_Ch[MROWS * EMB];    // ctx hi split, [s,b,e]
__device__ __nv_bfloat16 g_Cm[MROWS * EMB];    // ctx mid split

// ---------------------------------------------------------------------------
// Helpers (sm_103 plain: mma.sync + cp.async only)
// ---------------------------------------------------------------------------
__device__ __forceinline__ uint32_t smem_u32(const void* p) {
    uint32_t a;
    asm("{ .reg .u64 t; cvta.to.shared.u64 t, %1; cvt.u32.u64 %0, t; }"
        : "=r"(a) : "l"(p));
    return a;
}

__device__ __forceinline__ void cp16(uint32_t dst, const void* src) {
    asm volatile("cp.async.cg.shared.global [%0], [%1], 16;" :: "r"(dst), "l"(src));
}

__device__ __forceinline__ float tf32_rna(float x) {
    uint32_t u;
    asm("cvt.rna.tf32.f32 %0, %1;" : "=r"(u) : "f"(x));
    return __uint_as_float(u);
}

__device__ __forceinline__ uint16_t bf16_bits(float x) {
    return __bfloat16_as_ushort(__float2bfloat16(x));
}
__device__ __forceinline__ float bf16_val(float x, uint16_t& bits) {
    __nv_bfloat16 h = __float2bfloat16(x);
    bits = __bfloat16_as_ushort(h);
    return __bfloat162float(h);
}

// tf32 MMA: D += A(16x8) * B(8x8)^T
__device__ __forceinline__ void mma8(float* c, const uint32_t* a, const uint32_t* b) {
    asm volatile(
        "mma.sync.aligned.m16n8k8.row.col.f32.tf32.tf32.f32 "
        "{%0,%1,%2,%3}, {%4,%5,%6,%7}, {%8,%9}, {%0,%1,%2,%3};"
        : "+f"(c[0]), "+f"(c[1]), "+f"(c[2]), "+f"(c[3])
        : "r"(a[0]), "r"(a[1]), "r"(a[2]), "r"(a[3]), "r"(b[0]), "r"(b[1]));
}

// bf16 MMA: D += A(16x16) * B(16x8)^T
__device__ __forceinline__ void mma16(float* c, const uint32_t* a, const uint32_t* b) {
    asm volatile(
        "mma.sync.aligned.m16n8k16.row.col.f32.bf16.bf16.f32 "
        "{%0,%1,%2,%3}, {%4,%5,%6,%7}, {%8,%9}, {%0,%1,%2,%3};"
        : "+f"(c[0]), "+f"(c[1]), "+f"(c[2]), "+f"(c[3])
        : "r"(a[0]), "r"(a[1]), "r"(a[2]), "r"(a[3]), "r"(b[0]), "r"(b[1]));
}

// ---------------------------------------------------------------------------
// Split kernel: x -> (hi = bf16(x), mid = bf16(x - hi)), packed 2x bf16/u32
// ---------------------------------------------------------------------------
__global__ __launch_bounds__(256) void split_bf16_kernel(
    const float4* __restrict__ src, uint2* __restrict__ hi,
    uint2* __restrict__ mid, int n4)
{
    int i = blockIdx.x * 256 + threadIdx.x;
    if (i >= n4) return;
    float4 x = src[i];
    float xs[4] = {x.x, x.y, x.z, x.w};
    uint16_t h[4], m[4];
    #pragma unroll
    for (int j = 0; j < 4; j++) {
        float hv = bf16_val(xs[j], h[j]);
        m[j] = bf16_bits(xs[j] - hv);
    }
    hi[i]  = make_uint2((uint32_t)h[0] | ((uint32_t)h[1] << 16),
                        (uint32_t)h[2] | ((uint32_t)h[3] << 16));
    mid[i] = make_uint2((uint32_t)m[0] | ((uint32_t)m[1] << 16),
                        (uint32_t)m[2] | ((uint32_t)m[3] << 16));
}

// ---------------------------------------------------------------------------
// bf16x3 GEMM via mma.sync: C[M,N] = A[M,1024] @ B[N,1024]^T + bias[N]
// Block 128x128, BK=32, 2-stage cp.async, 256 threads.
// 8 warps in 2(m)x4(n); warp tile 64x32 = 4x4 m16n8k16 tiles.
// 3 MMAs per tile per k16: Ah*Bh + Ah*Bm + Am*Bh.
// Smem row stride 40 bf16 (80B) -> all 4B fragment loads conflict-free.
// ---------------------------------------------------------------------------
#define BKE   32                  // K elements per chunk
#define RS    40                  // smem row stride in bf16 elements
#define TILE_E (128*RS)           // 5120 bf16 per tile
#define TILE_B (TILE_E*2)         // 10240 bytes
#define STAGE_E (4*TILE_E)
#define STAGE_B (4*TILE_B)        // 40960 bytes
#define G_SMEM (2*STAGE_B)        // 81920 bytes
#define NCHUNK (1024/BKE)         // 32

template<int MODE>
__global__ __launch_bounds__(256, 1)
void tc_gemm(const __nv_bfloat16* __restrict__ Ah, const __nv_bfloat16* __restrict__ Am,
             const __nv_bfloat16* __restrict__ Bh, const __nv_bfloat16* __restrict__ Bm,
             const float* __restrict__ bias, float* __restrict__ Cout)
{
    extern __shared__ __nv_bfloat16 smbf[];
    const int tid  = threadIdx.x;
    const int wid  = tid >> 5;
    const int lane = tid & 31;
    const int m0 = blockIdx.y * 128;
    const int n0 = blockIdx.x * 128;
    const int warp_m = (wid & 1) * 64;
    const int warp_n = (wid >> 1) * 32;
    const int lr = lane >> 2;
    const int lc = lane & 3;

    float acc[4][4][4];
    #pragma unroll
    for (int mt = 0; mt < 4; mt++)
        #pragma unroll
        for (int nt = 0; nt < 4; nt++)
            #pragma unroll
            for (int r = 0; r < 4; r++) acc[mt][nt][r] = 0.0f;

    const uint32_t smb = smem_u32(smbf);

    // chunk loader: 4 tensors x 128 rows x 4 x 16B; 2 cp16/thread/tensor
    auto load_chunk = [&](int st, int k0) {
        const uint32_t sb = smb + (uint32_t)st * STAGE_B;
        #pragma unroll
        for (int i = 0; i < 2; i++) {
            const int idx = tid + i * 256;
            const int r = idx >> 2, q = idx & 3;
            const uint32_t o = (uint32_t)r * (RS * 2) + (uint32_t)q * 16;
            const size_t ga = (size_t)(m0 + r) * 1024 + k0 + q * 8;
            const size_t gb = (size_t)(n0 + r) * 1024 + k0 + q * 8;
            cp16(sb + 0 * TILE_B + o, Ah + ga);
            cp16(sb + 1 * TILE_B + o, Am + ga);
            cp16(sb + 2 * TILE_B + o, Bh + gb);
            cp16(sb + 3 * TILE_B + o, Bm + gb);
        }
        asm volatile("cp.async.commit_group;" ::: "memory");
    };

    load_chunk(0, 0);
    load_chunk(1, BKE);

    for (int c = 0; c < NCHUNK; c++) {
        if (c < NCHUNK - 1) asm volatile("cp.async.wait_group 1;" ::: "memory");
        else                asm volatile("cp.async.wait_group 0;" ::: "memory");
        __syncthreads();

        const __nv_bfloat16* As_h = smbf + (c & 1) * STAGE_E;
        const __nv_bfloat16* As_m = As_h + TILE_E;
        const __nv_bfloat16* Bs_h = As_h + 2 * TILE_E;
        const __nv_bfloat16* Bs_m = As_h + 3 * TILE_E;

        #pragma unroll
        for (int ks = 0; ks < 2; ks++) {
            const int kb = ks * 16 + 2 * lc;
            uint32_t ah[4][4], am[4][4], bh[4][2], bm[4][2];
            #pragma unroll
            for (int mt = 0; mt < 4; mt++) {
                const int row = warp_m + mt * 16 + lr;
                const __nv_bfloat16* ph = As_h + row * RS + kb;
                const __nv_bfloat16* pm = As_m + row * RS + kb;
                ah[mt][0] = *(const uint32_t*)(ph);
                ah[mt][1] = *(const uint32_t*)(ph + 8 * RS);
                ah[mt][2] = *(const uint32_t*)(ph + 8);
                ah[mt][3] = *(const uint32_t*)(ph + 8 * RS + 8);
                am[mt][0] = *(const uint32_t*)(pm);
                am[mt][1] = *(const uint32_t*)(pm + 8 * RS);
                am[mt][2] = *(const uint32_t*)(pm + 8);
                am[mt][3] = *(const uint32_t*)(pm + 8 * RS + 8);
            }
            #pragma unroll
            for (int nt = 0; nt < 4; nt++) {
                const int row = warp_n + nt * 8 + lr;
                const __nv_bfloat16* ph = Bs_h + row * RS + kb;
                const __nv_bfloat16* pm = Bs_m + row * RS + kb;
                bh[nt][0] = *(const uint32_t*)(ph);
                bh[nt][1] = *(const uint32_t*)(ph + 8);
                bm[nt][0] = *(const uint32_t*)(pm);
                bm[nt][1] = *(const uint32_t*)(pm + 8);
            }
            #pragma unroll
            for (int mt = 0; mt < 4; mt++)
                #pragma unroll
                for (int nt = 0; nt < 4; nt++) {
                    mma16(acc[mt][nt], ah[mt], bh[nt]);
                    mma16(acc[mt][nt], ah[mt], bm[nt]);
                    mma16(acc[mt][nt], am[mt], bh[nt]);
                }
        }
        __syncthreads();
        if (c + 2 < NCHUNK) load_chunk(c & 1, (c + 2) * BKE);
    }

    // ---- Epilogue: direct global stores (pairs of consecutive n) ----
    #pragma unroll
    for (int mt = 0; mt < 4; mt++) {
        #pragma unroll
        for (int nt = 0; nt < 4; nt++) {
            const int gm = m0 + warp_m + mt * 16 + lr;
            const int gn = n0 + warp_n + nt * 8 + lc * 2;
            #pragma unroll
            for (int half = 0; half < 2; half++) {
                const int m = gm + half * 8;
                const float v0 = acc[mt][nt][half * 2 + 0] + __ldg(&bias[gn]);
                const float v1 = acc[mt][nt][half * 2 + 1] + __ldg(&bias[gn + 1]);
                if (MODE == 0) {
                    const int s = m >> 3;
                    const int b = m & 7;
                    const int h = gn / 192;
                    const int cc = gn - h * 192;
                    const int w = cc >> 6;           // 0=Q,1=K,2=V (pair never straddles)
                    const int d = cc & 63;
                    const size_t idx = ((size_t)(b * NH + h) * SEQ + s) * HD + d;
                    if (w == 0)      { g_Q[idx] = v0 * 0.125f; g_Q[idx + 1] = v1 * 0.125f; }
                    else if (w == 1) { g_K[idx] = v0;          g_K[idx + 1] = v1; }
                    else             { g_V[idx] = v0;          g_V[idx + 1] = v1; }
                } else {
                    Cout[(size_t)m * 1024 + gn]     = v0;
                    Cout[(size_t)m * 1024 + gn + 1] = v1;
                }
            }
        }
    }
}

// ---------------------------------------------------------------------------
// Tensor-core flash attention (R8 passing version; epilogue now emits bf16
// hi/mid ctx splits for the bf16x3 out-proj).
// ---------------------------------------------------------------------------
#define XSTR 136
#define VSTRK 136
#define ATTN2_SMEM (35584 * 4)

__global__ __launch_bounds__(256, 1) void attn_tc_kernel()
{
    extern __shared__ float sh[];
    float* Qd   = sh;                    // [64][136]  q-major, 2d+{hi,lo}
    float* Kd   = Qd + 64 * XSTR;        // [64][136]  k-major, 2d+{hi,lo}
    float* Vd   = Kd + 64 * XSTR;        // [64][136]  k-major, 2d+{hi,lo}
    float* Pd   = Vd + 64 * VSTRK;       // [64][136]  q-major, 2k+{hi,lo}
    float* wmax = Pd + 64 * XSTR;        // [4][64]
    float* wsum = wmax + 256;            // [4][64]
    float* mrun = wsum + 256;            // [64]
    float* lrun = mrun + 64;             // [64]
    float* ssc  = lrun + 64;             // [64]
    float* mnew = ssc + 64;              // [64]

    const int tid  = threadIdx.x;
    const int wid  = tid >> 5;
    const int lane = tid & 31;
    const int lr = lane >> 2;
    const int lc = lane & 3;
    const int n  = blockIdx.y;           // head (b*16+h)
    const int qt = blockIdx.x;
    const int warp_m = (wid & 1) * 32;
    const int warp_n = (wid >> 1) * 16;
    const int wcol   = wid >> 1;

    const float* Qg = g_Q + ((size_t)n * SEQ + qt * 64) * HD;
    const float* Kg = g_K + (size_t)n * SEQ * HD;
    const float* Vg = g_V + (size_t)n * SEQ * HD;

    // Stage Q (split, interleaved)
    for (int i = tid; i < 64 * 16; i += 256) {
        const int r = i >> 4, c4 = (i & 15) << 2;
        float4 v = *(const float4*)(Qg + r * HD + c4);
        float hx = tf32_rna(v.x), hy = tf32_rna(v.y);
        float hz = tf32_rna(v.z), hw = tf32_rna(v.w);
        float* q = &Qd[r * XSTR + c4 * 2];
        *(float4*)(q)     = make_float4(hx, tf32_rna(v.x - hx), hy, tf32_rna(v.y - hy));
        *(float4*)(q + 4) = make_float4(hz, tf32_rna(v.z - hz), hw, tf32_rna(v.w - hw));
    }
    if (tid < 64) { mrun[tid] = -CUDART_INF_F; lrun[tid] = 0.f; }
    __syncthreads();

    // Hoist Q fragments to registers (tile-invariant): qh/ql [mt][ks][4]
    uint32_t qh[2][8][4], ql[2][8][4];
    #pragma unroll
    for (int mt = 0; mt < 2; mt++) {
        const float* base = &Qd[(warp_m + mt * 16) * XSTR];
        #pragma unroll
        for (int ks = 0; ks < 8; ks++) {
            const int k2 = 2 * (ks * 8 + lc);
            uint2 f0 = *(const uint2*)&base[lr * XSTR + k2];
            uint2 f1 = *(const uint2*)&base[(lr + 8) * XSTR + k2];
            uint2 f2 = *(const uint2*)&base[lr * XSTR + k2 + 8];
            uint2 f3 = *(const uint2*)&base[(lr + 8) * XSTR + k2 + 8];
            qh[mt][ks][0] = f0.x; ql[mt][ks][0] = f0.y;
            qh[mt][ks][1] = f1.x; ql[mt][ks][1] = f1.y;
            qh[mt][ks][2] = f2.x; ql[mt][ks][2] = f2.y;
            qh[mt][ks][3] = f3.x; ql[mt][ks][3] = f3.y;
        }
    }

    float o[2][2][4];
    #pragma unroll
    for (int mt = 0; mt < 2; mt++)
        #pragma unroll
        for (int nt = 0; nt < 2; nt++)
            #pragma unroll
            for (int r = 0; r < 4; r++) o[mt][nt][r] = 0.f;

    for (int kt = 0; kt < 16; kt++) {
        __syncthreads();   // prev-iter readers of Kd/Vd/Pd done
        // Stage K,V (split, interleaved)
        for (int i = tid; i < 64 * 16; i += 256) {
            const int r = i >> 4, c4 = (i & 15) << 2;
            const size_t go = (size_t)(kt * 64 + r) * HD + c4;
            float4 kv = *(const float4*)(Kg + go);
            float4 vv = *(const float4*)(Vg + go);
            float hx, hy, hz, hw;
            hx = tf32_rna(kv.x); hy = tf32_rna(kv.y);
            hz = tf32_rna(kv.z); hw = tf32_rna(kv.w);
            float* kd = &Kd[r * XSTR + c4 * 2];
            *(float4*)(kd)     = make_float4(hx, tf32_rna(kv.x - hx), hy, tf32_rna(kv.y - hy));
            *(float4*)(kd + 4) = make_float4(hz, tf32_rna(kv.z - hz), hw, tf32_rna(kv.w - hw));
            hx = tf32_rna(vv.x); hy = tf32_rna(vv.y);
            hz = tf32_rna(vv.z); hw = tf32_rna(vv.w);
            float* vd = &Vd[r * VSTRK + c4 * 2];
            *(float4*)(vd)     = make_float4(hx, tf32_rna(vv.x - hx), hy, tf32_rna(vv.y - hy));
            *(float4*)(vd + 4) = make_float4(hz, tf32_rna(vv.z - hz), hw, tf32_rna(vv.w - hw));
        }
        __syncthreads();

        // ---- S = Q @ K^T (tf32x3) ----
        float s[2][2][4];
        #pragma unroll
        for (int mt = 0; mt < 2; mt++)
            #pragma unroll
            for (int nt = 0; nt < 2; nt++)
                #pragma unroll
                for (int r = 0; r < 4; r++) s[mt][nt][r] = 0.f;

        #pragma unroll
        for (int ks = 0; ks < 8; ks++) {
            uint32_t bh[2][2], bl[2][2];
            #pragma unroll
            for (int nt = 0; nt < 2; nt++) {
                const float* kb = &Kd[(warp_n + nt * 8 + lr) * XSTR + 2 * (ks * 8 + lc)];
                uint2 f0 = *(const uint2*)kb;
                uint2 f1 = *(const uint2*)(kb + 8);
                bh[nt][0] = f0.x; bl[nt][0] = f0.y;
                bh[nt][1] = f1.x; bl[nt][1] = f1.y;
            }
            #pragma unroll
            for (int mt = 0; mt < 2; mt++)
                #pragma unroll
                for (int nt = 0; nt < 2; nt++) {
                    mma8(s[mt][nt], qh[mt][ks], bh[nt]);
                    mma8(s[mt][nt], qh[mt][ks], bl[nt]);
                    mma8(s[mt][nt], ql[mt][ks], bh[nt]);
                }
        }

        // ---- row max partials ----
        #pragma unroll
        for (int mt = 0; mt < 2; mt++) {
            float m0 = fmaxf(fmaxf(s[mt][0][0], s[mt][0][1]), fmaxf(s[mt][1][0], s[mt][1][1]));
            float m1 = fmaxf(fmaxf(s[mt][0][2], s[mt][0][3]), fmaxf(s[mt][1][2], s[mt][1][3]));
            m0 = fmaxf(m0, __shfl_xor_sync(0xffffffffu, m0, 1));
            m0 = fmaxf(m0, __shfl_xor_sync(0xffffffffu, m0, 2));
            m1 = fmaxf(m1, __shfl_xor_sync(0xffffffffu, m1, 1));
            m1 = fmaxf(m1, __shfl_xor_sync(0xffffffffu, m1, 2));
            if (lc == 0) {
                wmax[wcol * 64 + warp_m + mt * 16 + lr]     = m0;
                wmax[wcol * 64 + warp_m + mt * 16 + lr + 8] = m1;
            }
        }
        __syncthreads();
        if (tid < 64) {
            const float mo = mrun[tid];
            float mn = fmaxf(fmaxf(wmax[tid], wmax[64 + tid]),
                             fmaxf(wmax[128 + tid], wmax[192 + tid]));
            mn = fmaxf(mn, mo);
            mnew[tid] = mn;
            ssc[tid]  = __expf(mo - mn);
            mrun[tid] = mn;
        }
        __syncthreads();

        // ---- P = exp(S - mnew), sums, store hi/lo, rescale O ----
        #pragma unroll
        for (int mt = 0; mt < 2; mt++) {
            const int r0 = warp_m + mt * 16 + lr;
            const float mn0 = mnew[r0], mn1 = mnew[r0 + 8];
            float ps0 = 0.f, ps1 = 0.f;
            #pragma unroll
            for (int nt = 0; nt < 2; nt++) {
                const float p0 = __expf(s[mt][nt][0] - mn0);
                const float p1 = __expf(s[mt][nt][1] - mn0);
                const float p2 = __expf(s[mt][nt][2] - mn1);
                const float p3 = __expf(s[mt][nt][3] - mn1);
                ps0 += p0 + p1; ps1 += p2 + p3;
                const float h0 = tf32_rna(p0), h1 = tf32_rna(p1);
                const float h2 = tf32_rna(p2), h3 = tf32_rna(p3);
                const int cbase = 2 * (warp_n + nt * 8 + 2 * lc);
                *(float4*)&Pd[r0 * XSTR + cbase] =
                    make_float4(h0, tf32_rna(p0 - h0), h1, tf32_rna(p1 - h1));
                *(float4*)&Pd[(r0 + 8) * XSTR + cbase] =
                    make_float4(h2, tf32_rna(p2 - h2), h3, tf32_rna(p3 - h3));
            }
            ps0 += __shfl_xor_sync(0xffffffffu, ps0, 1);
            ps0 += __shfl_xor_sync(0xffffffffu, ps0, 2);
            ps1 += __shfl_xor_sync(0xffffffffu, ps1, 1);
            ps1 += __shfl_xor_sync(0xffffffffu, ps1, 2);
            if (lc == 0) {
                wsum[wcol * 64 + r0]     = ps0;
                wsum[wcol * 64 + r0 + 8] = ps1;
            }
            const float sc0 = ssc[r0], sc1 = ssc[r0 + 8];
            #pragma unroll
            for (int nt = 0; nt < 2; nt++) {
                o[mt][nt][0] *= sc0; o[mt][nt][1] *= sc0;
                o[mt][nt][2] *= sc1; o[mt][nt][3] *= sc1;
            }
        }
        __syncthreads();
        if (tid < 64)
            lrun[tid] = lrun[tid] * ssc[tid]
                      + (wsum[tid] + wsum[64 + tid] + wsum[128 + tid] + wsum[192 + tid]);

        // ---- O += P @ V (P exact hi/lo, V hi/lo, 3 terms) ----
        #pragma unroll
        for (int ks = 0; ks < 8; ks++) {
            uint32_t vh[2][2], vl[2][2];
            #pragma unroll
            for (int nt = 0; nt < 2; nt++) {
                const float* vb = &Vd[(ks * 8 + lc) * VSTRK + 2 * (warp_n + nt * 8 + lr)];
                uint2 f0 = *(const uint2*)vb;
                uint2 f1 = *(const uint2*)(vb + 4 * VSTRK);
                vh[nt][0] = f0.x; vl[nt][0] = f0.y;
                vh[nt][1] = f1.x; vl[nt][1] = f1.y;
            }
            #pragma unroll
            for (int mt = 0; mt < 2; mt++) {
                const float* pb = &Pd[(warp_m + mt * 16) * XSTR];
                const int k2 = 2 * (ks * 8 + lc);
                uint2 f0 = *(const uint2*)&pb[lr * XSTR + k2];
                uint2 f1 = *(const uint2*)&pb[(lr + 8) * XSTR + k2];
                uint2 f2 = *(const uint2*)&pb[lr * XSTR + k2 + 8];
                uint2 f3 = *(const uint2*)&pb[(lr + 8) * XSTR + k2 + 8];
                uint32_t ph[4] = {f0.x, f1.x, f2.x, f3.x};
                uint32_t pl[4] = {f0.y, f1.y, f2.y, f3.y};
                #pragma unroll
                for (int nt = 0; nt < 2; nt++) {
                    mma8(o[mt][nt], ph, vh[nt]);
                    mma8(o[mt][nt], ph, vl[nt]);
                    mma8(o[mt][nt], pl, vh[nt]);
                }
            }
        }
    }

    __syncthreads();
    // Normalize and store ctx bf16 hi/mid splits to [s,b,e]
    const int b = n >> 4;
    const int h = n & 15;
    #pragma unroll
    for (int mt = 0; mt < 2; mt++) {
        const int r0 = warp_m + mt * 16 + lr;
        const float li0 = 1.0f / lrun[r0];
        const float li1 = 1.0f / lrun[r0 + 8];
        #pragma unroll
        for (int nt = 0; nt < 2; nt++) {
            const int d = warp_n + nt * 8 + 2 * lc;
            #pragma unroll
            for (int half = 0; half < 2; half++) {
                const int row = r0 + half * 8;
                const float li = half ? li1 : li0;
                const float v0 = o[mt][nt][half * 2 + 0] * li;
                const float v1 = o[mt][nt][half * 2 + 1] * li;
                const size_t addr = ((size_t)(qt * 64 + row) * BATCH + b) * EMB + h * HD + d;
                uint16_t h0, h1;
                const float hv0 = bf16_val(v0, h0);
                const float hv1 = bf16_val(v1, h1);
                const uint16_t m0b = bf16_bits(v0 - hv0);
                const uint16_t m1b = bf16_bits(v1 - hv1);
                *(uint32_t*)&g_Ch[addr] = (uint32_t)h0 | ((uint32_t)h1 << 16);
                *(uint32_t*)&g_Cm[addr] = (uint32_t)m0b | ((uint32_t)m1b << 16);
            }
        }
    }
}

// ---------------------------------------------------------------------------
extern "C" void kernel_launch(void* const* d_in, const int* in_sizes, int n_in,
                              void* d_out, int out_size)
{
    const float* X  = (const float*)d_in[0];  // query [S,B,E]
    const float* Wq = (const float*)d_in[3];  // in_proj_w [3E,E]
    const float* bq = (const float*)d_in[4];  // in_proj_b [3E]
    const float* Wo = (const float*)d_in[5];  // out_proj_w [E,E]
    const float* bo = (const float*)d_in[6];  // out_proj_b [E]
    float* out = (float*)d_out;

    cudaFuncSetAttribute(attn_tc_kernel,
                         cudaFuncAttributeMaxDynamicSharedMemorySize, ATTN2_SMEM);
    cudaFuncSetAttribute(tc_gemm<0>,
                         cudaFuncAttributeMaxDynamicSharedMemorySize, G_SMEM);
    cudaFuncSetAttribute(tc_gemm<1>,
                         cudaFuncAttributeMaxDynamicSharedMemorySize, G_SMEM);

    __nv_bfloat16 *xh, *xm, *wqh, *wqm, *woh, *wom, *ch, *cm;
    cudaGetSymbolAddress((void**)&xh,  g_Xh);
    cudaGetSymbolAddress((void**)&xm,  g_Xm);
    cudaGetSymbolAddress((void**)&wqh, g_Wqh);
    cudaGetSymbolAddress((void**)&wqm, g_Wqm);
    cudaGetSymbolAddress((void**)&woh, g_Woh);
    cudaGetSymbolAddress((void**)&wom, g_Wom);
    cudaGetSymbolAddress((void**)&ch,  g_Ch);
    cudaGetSymbolAddress((void**)&cm,  g_Cm);

    // 0) bf16 hi/mid splits of inputs and weights
    split_bf16_kernel<<<(MROWS*EMB/4 + 255)/256, 256>>>(
        (const float4*)X, (uint2*)xh, (uint2*)xm, MROWS*EMB/4);
    split_bf16_kernel<<<(3*EMB*EMB/4 + 255)/256, 256>>>(
        (const float4*)Wq, (uint2*)wqh, (uint2*)wqm, 3*EMB*EMB/4);
    split_bf16_kernel<<<(EMB*EMB/4 + 255)/256, 256>>>(
        (const float4*)Wo, (uint2*)woh, (uint2*)wom, EMB*EMB/4);

    // 1) QKV projection (mma.sync bf16x3) + scatter into g_Q/g_K/g_V
    tc_gemm<0><<<dim3(3072/128, MROWS/128), 256, G_SMEM>>>(xh, xm, wqh, wqm, bq, nullptr);

    // 2) Tensor-core flash attention — writes ctx bf16 hi/mid splits
    attn_tc_kernel<<<dim3(SEQ/64, NHEADS_TOT), 256, ATTN2_SMEM>>>();

    // 3) Output projection (mma.sync bf16x3)
    tc_gemm<1><<<dim3(1024/128, MROWS/128), 256, G_SMEM>>>(ch, cm, woh, wom, bo, out);
}

// round 12
// speedup vs baseline: 1.9683x; 1.5271x over previous
#include <cuda_runtime.h>
#include <cuda_bf16.h>
#include <math_constants.h>
#include <cstdint>

// Problem constants
#define SEQ   1024
#define BATCH 8
#define EMB   1024
#define NH    16
#define HD    64
#define MROWS (SEQ*BATCH)        // 8192
#define NHEADS_TOT (BATCH*NH)    // 128

// ---------------------------------------------------------------------------
// Scratch (device globals; allocation-free)
// ---------------------------------------------------------------------------
__device__ float g_Q[NHEADS_TOT * SEQ * HD];   // [n][s][d], pre-scaled by 1/8
__device__ float g_K[NHEADS_TOT * SEQ * HD];
__device__ float g_V[NHEADS_TOT * SEQ * HD];
__device__ __nv_bfloat16 g_Xh[MROWS * EMB];
__device__ __nv_bfloat16 g_Xm[MROWS * EMB];
__device__ __nv_bfloat16 g_Wqh[3 * EMB * EMB];
__device__ __nv_bfloat16 g_Wqm[3 * EMB * EMB];
__device__ __nv_bfloat16 g_Woh[EMB * EMB];
__device__ __nv_bfloat16 g_Wom[EMB * EMB];
__device__ __nv_bfloat16 g_Ch[MROWS * EMB];    // ctx hi split, [s,b,e]
__device__ __nv_bfloat16 g_Cm[MROWS * EMB];    // ctx mid split

// ---------------------------------------------------------------------------
// Helpers (sm_103 plain: mma.sync + cp.async + ldmatrix only)
// ---------------------------------------------------------------------------
__device__ __forceinline__ uint32_t smem_u32(const void* p) {
    uint32_t a;
    asm("{ .reg .u64 t; cvta.to.shared.u64 t, %1; cvt.u32.u64 %0, t; }"
        : "=r"(a) : "l"(p));
    return a;
}

__device__ __forceinline__ void cp16(uint32_t dst, const void* src) {
    asm volatile("cp.async.cg.shared.global [%0], [%1], 16;" :: "r"(dst), "l"(src));
}

__device__ __forceinline__ uint16_t bf16_bits(float x) {
    return __bfloat16_as_ushort(__float2bfloat16(x));
}
__device__ __forceinline__ float bf16_val(float x, uint16_t& bits) {
    __nv_bfloat16 h = __float2bfloat16(x);
    bits = __bfloat16_as_ushort(h);
    return __bfloat162float(h);
}

// bf16 MMA: D += A(16x16) * B(16x8)^T
__device__ __forceinline__ void mma16(float* c, const uint32_t* a, const uint32_t* b) {
    asm volatile(
        "mma.sync.aligned.m16n8k16.row.col.f32.bf16.bf16.f32 "
        "{%0,%1,%2,%3}, {%4,%5,%6,%7}, {%8,%9}, {%0,%1,%2,%3};"
        : "+f"(c[0]), "+f"(c[1]), "+f"(c[2]), "+f"(c[3])
        : "r"(a[0]), "r"(a[1]), "r"(a[2]), "r"(a[3]), "r"(b[0]), "r"(b[1]));
}

__device__ __forceinline__ void ldsm_x4(uint32_t* r, uint32_t addr) {
    asm volatile("ldmatrix.sync.aligned.m8n8.x4.shared.b16 {%0,%1,%2,%3}, [%4];"
        : "=r"(r[0]), "=r"(r[1]), "=r"(r[2]), "=r"(r[3]) : "r"(addr));
}
__device__ __forceinline__ void ldsm_x4_t(uint32_t* r, uint32_t addr) {
    asm volatile("ldmatrix.sync.aligned.m8n8.x4.trans.shared.b16 {%0,%1,%2,%3}, [%4];"
        : "=r"(r[0]), "=r"(r[1]), "=r"(r[2]), "=r"(r[3]) : "r"(addr));
}

// float4 -> packed bf16 hi / mid uint2
__device__ __forceinline__ void split4(float4 v, uint2& h, uint2& m) {
    uint16_t hb0, hb1, hb2, hb3;
    float h0 = bf16_val(v.x, hb0);
    float h1 = bf16_val(v.y, hb1);
    float h2 = bf16_val(v.z, hb2);
    float h3 = bf16_val(v.w, hb3);
    uint16_t m0 = bf16_bits(v.x - h0), m1 = bf16_bits(v.y - h1);
    uint16_t m2 = bf16_bits(v.z - h2), m3 = bf16_bits(v.w - h3);
    h = make_uint2((uint32_t)hb0 | ((uint32_t)hb1 << 16),
                   (uint32_t)hb2 | ((uint32_t)hb3 << 16));
    m = make_uint2((uint32_t)m0 | ((uint32_t)m1 << 16),
                   (uint32_t)m2 | ((uint32_t)m3 << 16));
}

// ---------------------------------------------------------------------------
// Split kernel: x -> (hi = bf16(x), mid = bf16(x - hi)), packed 2x bf16/u32
// ---------------------------------------------------------------------------
__global__ __launch_bounds__(256) void split_bf16_kernel(
    const float4* __restrict__ src, uint2* __restrict__ hi,
    uint2* __restrict__ mid, int n4)
{
    int i = blockIdx.x * 256 + threadIdx.x;
    if (i >= n4) return;
    uint2 h, m;
    split4(src[i], h, m);
    hi[i] = h; mid[i] = m;
}

// ---------------------------------------------------------------------------
// bf16x3 GEMM via mma.sync (unchanged from R10 passing version)
// ---------------------------------------------------------------------------
#define BKE   32
#define RS    40
#define TILE_E (128*RS)
#define TILE_B (TILE_E*2)
#define STAGE_E (4*TILE_E)
#define STAGE_B (4*TILE_B)
#define G_SMEM (2*STAGE_B)
#define NCHUNK (1024/BKE)

template<int MODE>
__global__ __launch_bounds__(256, 1)
void tc_gemm(const __nv_bfloat16* __restrict__ Ah, const __nv_bfloat16* __restrict__ Am,
             const __nv_bfloat16* __restrict__ Bh, const __nv_bfloat16* __restrict__ Bm,
             const float* __restrict__ bias, float* __restrict__ Cout)
{
    extern __shared__ __nv_bfloat16 smbf[];
    const int tid  = threadIdx.x;
    const int wid  = tid >> 5;
    const int lane = tid & 31;
    const int m0 = blockIdx.y * 128;
    const int n0 = blockIdx.x * 128;
    const int warp_m = (wid & 1) * 64;
    const int warp_n = (wid >> 1) * 32;
    const int lr = lane >> 2;
    const int lc = lane & 3;

    float acc[4][4][4];
    #pragma unroll
    for (int mt = 0; mt < 4; mt++)
        #pragma unroll
        for (int nt = 0; nt < 4; nt++)
            #pragma unroll
            for (int r = 0; r < 4; r++) acc[mt][nt][r] = 0.0f;

    const uint32_t smb = smem_u32(smbf);

    auto load_chunk = [&](int st, int k0) {
        const uint32_t sb = smb + (uint32_t)st * STAGE_B;
        #pragma unroll
        for (int i = 0; i < 2; i++) {
            const int idx = tid + i * 256;
            const int r = idx >> 2, q = idx & 3;
            const uint32_t o = (uint32_t)r * (RS * 2) + (uint32_t)q * 16;
            const size_t ga = (size_t)(m0 + r) * 1024 + k0 + q * 8;
            const size_t gb = (size_t)(n0 + r) * 1024 + k0 + q * 8;
            cp16(sb + 0 * TILE_B + o, Ah + ga);
            cp16(sb + 1 * TILE_B + o, Am + ga);
            cp16(sb + 2 * TILE_B + o, Bh + gb);
            cp16(sb + 3 * TILE_B + o, Bm + gb);
        }
        asm volatile("cp.async.commit_group;" ::: "memory");
    };

    load_chunk(0, 0);
    load_chunk(1, BKE);

    for (int c = 0; c < NCHUNK; c++) {
        if (c < NCHUNK - 1) asm volatile("cp.async.wait_group 1;" ::: "memory");
        else                asm volatile("cp.async.wait_group 0;" ::: "memory");
        __syncthreads();

        const __nv_bfloat16* As_h = smbf + (c & 1) * STAGE_E;
        const __nv_bfloat16* As_m = As_h + TILE_E;
        const __nv_bfloat16* Bs_h = As_h + 2 * TILE_E;
        const __nv_bfloat16* Bs_m = As_h + 3 * TILE_E;

        #pragma unroll
        for (int ks = 0; ks < 2; ks++) {
            const int kb = ks * 16 + 2 * lc;
            uint32_t ah[4][4], am[4][4], bh[4][2], bm[4][2];
            #pragma unroll
            for (int mt = 0; mt < 4; mt++) {
                const int row = warp_m + mt * 16 + lr;
                const __nv_bfloat16* ph = As_h + row * RS + kb;
                const __nv_bfloat16* pm = As_m + row * RS + kb;
                ah[mt][0] = *(const uint32_t*)(ph);
                ah[mt][1] = *(const uint32_t*)(ph + 8 * RS);
                ah[mt][2] = *(const uint32_t*)(ph + 8);
                ah[mt][3] = *(const uint32_t*)(ph + 8 * RS + 8);
                am[mt][0] = *(const uint32_t*)(pm);
                am[mt][1] = *(const uint32_t*)(pm + 8 * RS);
                am[mt][2] = *(const uint32_t*)(pm + 8);
                am[mt][3] = *(const uint32_t*)(pm + 8 * RS + 8);
            }
            #pragma unroll
            for (int nt = 0; nt < 4; nt++) {
                const int row = warp_n + nt * 8 + lr;
                const __nv_bfloat16* ph = Bs_h + row * RS + kb;
                const __nv_bfloat16* pm = Bs_m + row * RS + kb;
                bh[nt][0] = *(const uint32_t*)(ph);
                bh[nt][1] = *(const uint32_t*)(ph + 8);
                bm[nt][0] = *(const uint32_t*)(pm);
                bm[nt][1] = *(const uint32_t*)(pm + 8);
            }
            #pragma unroll
            for (int mt = 0; mt < 4; mt++)
                #pragma unroll
                for (int nt = 0; nt < 4; nt++) {
                    mma16(acc[mt][nt], ah[mt], bh[nt]);
                    mma16(acc[mt][nt], ah[mt], bm[nt]);
                    mma16(acc[mt][nt], am[mt], bh[nt]);
                }
        }
        __syncthreads();
        if (c + 2 < NCHUNK) load_chunk(c & 1, (c + 2) * BKE);
    }

    #pragma unroll
    for (int mt = 0; mt < 4; mt++) {
        #pragma unroll
        for (int nt = 0; nt < 4; nt++) {
            const int gm = m0 + warp_m + mt * 16 + lr;
            const int gn = n0 + warp_n + nt * 8 + lc * 2;
            #pragma unroll
            for (int half = 0; half < 2; half++) {
                const int m = gm + half * 8;
                const float v0 = acc[mt][nt][half * 2 + 0] + __ldg(&bias[gn]);
                const float v1 = acc[mt][nt][half * 2 + 1] + __ldg(&bias[gn + 1]);
                if (MODE == 0) {
                    const int s = m >> 3;
                    const int b = m & 7;
                    const int h = gn / 192;
                    const int cc = gn - h * 192;
                    const int w = cc >> 6;
                    const int d = cc & 63;
                    const size_t idx = ((size_t)(b * NH + h) * SEQ + s) * HD + d;
                    if (w == 0)      { g_Q[idx] = v0 * 0.125f; g_Q[idx + 1] = v1 * 0.125f; }
                    else if (w == 1) { g_K[idx] = v0;          g_K[idx + 1] = v1; }
                    else             { g_V[idx] = v0;          g_V[idx + 1] = v1; }
                } else {
                    Cout[(size_t)m * 1024 + gn]     = v0;
                    Cout[(size_t)m * 1024 + gn + 1] = v1;
                }
            }
        }
    }
}

// ---------------------------------------------------------------------------
// bf16x3 tensor-core flash attention. Block = (64 queries, head), 256 thr.
// 8 warps: warp_m=(wid&1)*32, warp_n=(wid>>1)*16. m16n8k16 bf16 MMAs.
// Planes (bf16, row stride 72 = 64 payload + 8 pad): Qh Qm Kh Km Vh Vm Ph Pm.
// Row byte stride 144 (16B-aligned); ldmatrix row addrs conflict-free.
// ---------------------------------------------------------------------------
#define ARS 72
#define PLANE_E (64*ARS)          // 4608 bf16 = 9216 B
#define ATTN3_SMEM (8*PLANE_E*2 + 768*4)   // 73728 + 3072 = 76800 B

__global__ __launch_bounds__(256, 2) void attn_tc_kernel()
{
    extern __shared__ __nv_bfloat16 shb[];
    __nv_bfloat16* Qh = shb;
    __nv_bfloat16* Qm = Qh + PLANE_E;
    __nv_bfloat16* Kh = Qm + PLANE_E;
    __nv_bfloat16* Km = Kh + PLANE_E;
    __nv_bfloat16* Vh = Km + PLANE_E;
    __nv_bfloat16* Vm = Vh + PLANE_E;
    __nv_bfloat16* Ph = Vm + PLANE_E;
    __nv_bfloat16* Pm = Ph + PLANE_E;
    float* wmax = (float*)(Pm + PLANE_E);   // [4][64]
    float* wsum = wmax + 256;               // [4][64]
    float* mrun = wsum + 256;
    float* lrun = mrun + 64;
    float* ssc  = lrun + 64;
    float* mnew = ssc + 64;

    const int tid  = threadIdx.x;
    const int wid  = tid >> 5;
    const int lane = tid & 31;
    const int lr = lane >> 2;
    const int lc = lane & 3;
    const int n  = blockIdx.y;           // head (b*16+h)
    const int qt = blockIdx.x;
    const int warp_m = (wid & 1) * 32;
    const int warp_n = (wid >> 1) * 16;
    const int wcol   = wid >> 1;

    const float* Qg = g_Q + ((size_t)n * SEQ + qt * 64) * HD;
    const float* Kg = g_K + (size_t)n * SEQ * HD;
    const float* Vg = g_V + (size_t)n * SEQ * HD;

    // ldmatrix lane-address offsets (bf16-element units within a plane)
    const int g8 = lane >> 3, l8 = lane & 7;
    const int aoff = ((g8 & 1) * 8 + l8) * ARS + (g8 >> 1) * 8;   // A (Q,P)
    const int boff = ((g8 >> 1) * 8 + l8) * ARS + (g8 & 1) * 8;   // B (K)
    const int voff = ((g8 & 1) * 8 + l8) * ARS + (g8 >> 1) * 8;   // V (trans)

    const uint32_t bQh = smem_u32(Qh), bQm = smem_u32(Qm);
    const uint32_t bKh = smem_u32(Kh), bKm = smem_u32(Km);
    const uint32_t bVh = smem_u32(Vh), bVm = smem_u32(Vm);
    const uint32_t bPh = smem_u32(Ph), bPm = smem_u32(Pm);

    // Stage Q
    for (int i = tid; i < 64 * 16; i += 256) {
        const int r = i >> 4, c4 = (i & 15) << 2;
        uint2 h, m;
        split4(*(const float4*)(Qg + r * HD + c4), h, m);
        *(uint2*)&Qh[r * ARS + c4] = h;
        *(uint2*)&Qm[r * ARS + c4] = m;
    }
    if (tid < 64) { mrun[tid] = -CUDART_INF_F; lrun[tid] = 0.f; }

    float o[2][2][4];
    #pragma unroll
    for (int mt = 0; mt < 2; mt++)
        #pragma unroll
        for (int nt = 0; nt < 2; nt++)
            #pragma unroll
            for (int r = 0; r < 4; r++) o[mt][nt][r] = 0.f;

    for (int kt = 0; kt < 16; kt++) {
        __syncthreads();   // prev-iter readers done (also covers Q staging)
        for (int i = tid; i < 64 * 16; i += 256) {
            const int r = i >> 4, c4 = (i & 15) << 2;
            const size_t go = (size_t)(kt * 64 + r) * HD + c4;
            uint2 h, m;
            split4(*(const float4*)(Kg + go), h, m);
            *(uint2*)&Kh[r * ARS + c4] = h;
            *(uint2*)&Km[r * ARS + c4] = m;
            split4(*(const float4*)(Vg + go), h, m);
            *(uint2*)&Vh[r * ARS + c4] = h;
            *(uint2*)&Vm[r * ARS + c4] = m;
        }
        __syncthreads();

        // ---- S = Q @ K^T (bf16x3) ----
        float s[2][2][4];
        #pragma unroll
        for (int mt = 0; mt < 2; mt++)
            #pragma unroll
            for (int nt = 0; nt < 2; nt++)
                #pragma unroll
                for (int r = 0; r < 4; r++) s[mt][nt][r] = 0.f;

        #pragma unroll
        for (int ks = 0; ks < 4; ks++) {
            uint32_t kh4[4], km4[4];
            const uint32_t kOff = 2u * (warp_n * ARS + ks * 16 + boff);
            ldsm_x4(kh4, bKh + kOff);
            ldsm_x4(km4, bKm + kOff);
            #pragma unroll
            for (int mt = 0; mt < 2; mt++) {
                uint32_t qh4[4], qm4[4];
                const uint32_t qOff = 2u * ((warp_m + mt * 16) * ARS + ks * 16 + aoff);
                ldsm_x4(qh4, bQh + qOff);
                ldsm_x4(qm4, bQm + qOff);
                #pragma unroll
                for (int nt = 0; nt < 2; nt++) {
                    mma16(s[mt][nt], qh4, &kh4[nt * 2]);
                    mma16(s[mt][nt], qh4, &km4[nt * 2]);
                    mma16(s[mt][nt], qm4, &kh4[nt * 2]);
                }
            }
        }

        // ---- row max partials ----
        #pragma unroll
        for (int mt = 0; mt < 2; mt++) {
            float m0 = fmaxf(fmaxf(s[mt][0][0], s[mt][0][1]), fmaxf(s[mt][1][0], s[mt][1][1]));
            float m1 = fmaxf(fmaxf(s[mt][0][2], s[mt][0][3]), fmaxf(s[mt][1][2], s[mt][1][3]));
            m0 = fmaxf(m0, __shfl_xor_sync(0xffffffffu, m0, 1));
            m0 = fmaxf(m0, __shfl_xor_sync(0xffffffffu, m0, 2));
            m1 = fmaxf(m1, __shfl_xor_sync(0xffffffffu, m1, 1));
            m1 = fmaxf(m1, __shfl_xor_sync(0xffffffffu, m1, 2));
            if (lc == 0) {
                wmax[wcol * 64 + warp_m + mt * 16 + lr]     = m0;
                wmax[wcol * 64 + warp_m + mt * 16 + lr + 8] = m1;
            }
        }
        __syncthreads();
        if (tid < 64) {
            const float mo = mrun[tid];
            float mn = fmaxf(fmaxf(wmax[tid], wmax[64 + tid]),
                             fmaxf(wmax[128 + tid], wmax[192 + tid]));
            mn = fmaxf(mn, mo);
            mnew[tid] = mn;
            ssc[tid]  = __expf(mo - mn);
            mrun[tid] = mn;
        }
        __syncthreads();

        // ---- P = exp(S - mnew) -> bf16 hi/mid planes, sums, rescale O ----
        #pragma unroll
        for (int mt = 0; mt < 2; mt++) {
            const int r0 = warp_m + mt * 16 + lr;
            const float mn0 = mnew[r0], mn1 = mnew[r0 + 8];
            float ps0 = 0.f, ps1 = 0.f;
            #pragma unroll
            for (int nt = 0; nt < 2; nt++) {
                const float p0 = __expf(s[mt][nt][0] - mn0);
                const float p1 = __expf(s[mt][nt][1] - mn0);
                const float p2 = __expf(s[mt][nt][2] - mn1);
                const float p3 = __expf(s[mt][nt][3] - mn1);
                ps0 += p0 + p1; ps1 += p2 + p3;
                uint16_t hb0, hb1, hb2, hb3;
                const float hv0 = bf16_val(p0, hb0);
                const float hv1 = bf16_val(p1, hb1);
                const float hv2 = bf16_val(p2, hb2);
                const float hv3 = bf16_val(p3, hb3);
                const int cbase = warp_n + nt * 8 + 2 * lc;
                *(uint32_t*)&Ph[r0 * ARS + cbase] =
                    (uint32_t)hb0 | ((uint32_t)hb1 << 16);
                *(uint32_t*)&Pm[r0 * ARS + cbase] =
                    (uint32_t)bf16_bits(p0 - hv0) | ((uint32_t)bf16_bits(p1 - hv1) << 16);
                *(uint32_t*)&Ph[(r0 + 8) * ARS + cbase] =
                    (uint32_t)hb2 | ((uint32_t)hb3 << 16);
                *(uint32_t*)&Pm[(r0 + 8) * ARS + cbase] =
                    (uint32_t)bf16_bits(p2 - hv2) | ((uint32_t)bf16_bits(p3 - hv3) << 16);
            }
            ps0 += __shfl_xor_sync(0xffffffffu, ps0, 1);
            ps0 += __shfl_xor_sync(0xffffffffu, ps0, 2);
            ps1 += __shfl_xor_sync(0xffffffffu, ps1, 1);
            ps1 += __shfl_xor_sync(0xffffffffu, ps1, 2);
            if (lc == 0) {
                wsum[wcol * 64 + r0]     = ps0;
                wsum[wcol * 64 + r0 + 8] = ps1;
            }
            const float sc0 = ssc[r0], sc1 = ssc[r0 + 8];
            #pragma unroll
            for (int nt = 0; nt < 2; nt++) {
                o[mt][nt][0] *= sc0; o[mt][nt][1] *= sc0;
                o[mt][nt][2] *= sc1; o[mt][nt][3] *= sc1;
            }
        }
        __syncthreads();
        if (tid < 64)
            lrun[tid] = lrun[tid] * ssc[tid]
                      + (wsum[tid] + wsum[64 + tid] + wsum[128 + tid] + wsum[192 + tid]);

        // ---- O += P @ V (bf16x3; V B-operand via ldmatrix.trans) ----
        #pragma unroll
        for (int ks = 0; ks < 4; ks++) {
            uint32_t vh4[4], vm4[4];
            const uint32_t vOff = 2u * (ks * 16 * ARS + warp_n + voff);
            ldsm_x4_t(vh4, bVh + vOff);
            ldsm_x4_t(vm4, bVm + vOff);
            #pragma unroll
            for (int mt = 0; mt < 2; mt++) {
                uint32_t ph4[4], pm4[4];
                const uint32_t pOff = 2u * ((warp_m + mt * 16) * ARS + ks * 16 + aoff);
                ldsm_x4(ph4, bPh + pOff);
                ldsm_x4(pm4, bPm + pOff);
                #pragma unroll
                for (int nt = 0; nt < 2; nt++) {
                    mma16(o[mt][nt], ph4, &vh4[nt * 2]);
                    mma16(o[mt][nt], ph4, &vm4[nt * 2]);
                    mma16(o[mt][nt], pm4, &vh4[nt * 2]);
                }
            }
        }
    }

    __syncthreads();
    // Normalize and store ctx bf16 hi/mid splits to [s,b,e]
    const int b = n >> 4;
    const int h = n & 15;
    #pragma unroll
    for (int mt = 0; mt < 2; mt++) {
        const int r0 = warp_m + mt * 16 + lr;
        const float li0 = 1.0f / lrun[r0];
        const float li1 = 1.0f / lrun[r0 + 8];
        #pragma unroll
        for (int nt = 0; nt < 2; nt++) {
            const int d = warp_n + nt * 8 + 2 * lc;
            #pragma unroll
            for (int half = 0; half < 2; half++) {
                const int row = r0 + half * 8;
                const float li = half ? li1 : li0;
                const float v0 = o[mt][nt][half * 2 + 0] * li;
                const float v1 = o[mt][nt][half * 2 + 1] * li;
                const size_t addr = ((size_t)(qt * 64 + row) * BATCH + b) * EMB + h * HD + d;
                uint16_t h0, h1;
                const float hv0 = bf16_val(v0, h0);
                const float hv1 = bf16_val(v1, h1);
                *(uint32_t*)&g_Ch[addr] = (uint32_t)h0 | ((uint32_t)h1 << 16);
                *(uint32_t*)&g_Cm[addr] =
                    (uint32_t)bf16_bits(v0 - hv0) | ((uint32_t)bf16_bits(v1 - hv1) << 16);
            }
        }
    }
}

// ---------------------------------------------------------------------------
extern "C" void kernel_launch(void* const* d_in, const int* in_sizes, int n_in,
                              void* d_out, int out_size)
{
    const float* X  = (const float*)d_in[0];  // query [S,B,E]
    const float* Wq = (const float*)d_in[3];  // in_proj_w [3E,E]
    const float* bq = (const float*)d_in[4];  // in_proj_b [3E]
    const float* Wo = (const float*)d_in[5];  // out_proj_w [E,E]
    const float* bo = (const float*)d_in[6];  // out_proj_b [E]
    float* out = (float*)d_out;

    cudaFuncSetAttribute(attn_tc_kernel,
                         cudaFuncAttributeMaxDynamicSharedMemorySize, ATTN3_SMEM);
    cudaFuncSetAttribute(tc_gemm<0>,
                         cudaFuncAttributeMaxDynamicSharedMemorySize, G_SMEM);
    cudaFuncSetAttribute(tc_gemm<1>,
                         cudaFuncAttributeMaxDynamicSharedMemorySize, G_SMEM);

    __nv_bfloat16 *xh, *xm, *wqh, *wqm, *woh, *wom, *ch, *cm;
    cudaGetSymbolAddress((void**)&xh,  g_Xh);
    cudaGetSymbolAddress((void**)&xm,  g_Xm);
    cudaGetSymbolAddress((void**)&wqh, g_Wqh);
    cudaGetSymbolAddress((void**)&wqm, g_Wqm);
    cudaGetSymbolAddress((void**)&woh, g_Woh);
    cudaGetSymbolAddress((void**)&wom, g_Wom);
    cudaGetSymbolAddress((void**)&ch,  g_Ch);
    cudaGetSymbolAddress((void**)&cm,  g_Cm);

    // 0) bf16 hi/mid splits of inputs and weights
    split_bf16_kernel<<<(MROWS*EMB/4 + 255)/256, 256>>>(
        (const float4*)X, (uint2*)xh, (uint2*)xm, MROWS*EMB/4);
    split_bf16_kernel<<<(3*EMB*EMB/4 + 255)/256, 256>>>(
        (const float4*)Wq, (uint2*)wqh, (uint2*)wqm, 3*EMB*EMB/4);
    split_bf16_kernel<<<(EMB*EMB/4 + 255)/256, 256>>>(
        (const float4*)Wo, (uint2*)woh, (uint2*)wom, EMB*EMB/4);

    // 1) QKV projection (mma.sync bf16x3) + scatter into g_Q/g_K/g_V
    tc_gemm<0><<<dim3(3072/128, MROWS/128), 256, G_SMEM>>>(xh, xm, wqh, wqm, bq, nullptr);

    // 2) bf16x3 tensor-core flash attention — writes ctx bf16 hi/mid splits
    attn_tc_kernel<<<dim3(SEQ/64, NHEADS_TOT), 256, ATTN3_SMEM>>>();

    // 3) Output projection (mma.sync bf16x3)
    tc_gemm<1><<<dim3(1024/128, MROWS/128), 256, G_SMEM>>>(ch, cm, woh, wom, bo, out);
}